// round 16
// baseline (speedup 1.0000x reference)
#include <cuda_runtime.h>
#include <cuda_fp16.h>
#include <cstdint>
#include <cstddef>

#define N_NODES 20000
#define N_EDGES 160000
#define MUL0 32
#define MUL1 16
#define NODE_DIM 80
#define EDGE_FEAT 128
#define HIDDEN 128
#define W_NUMEL 2560
#define MTILE 128
#define NTILES (N_EDGES / MTILE)      // 1250
#define NCHUNK 64
#define NCHUNKS (W_NUMEL / NCHUNK)    // 40
#define ETHREADS 128

#define C0f   0.14433756729740643f
#define C1f   0.21650635094610965f
#define IS3f  0.5773502691896258f
#define IS6f  0.40824829046386296f
#define C0IS3 (C0f * IS3f)
#define C1IS3 (C1f * IS3f)
#define C1IS6 (C1f * IS6f)
#define EPS_LN 1e-5f

// ---------------- device scratch ----------------
__device__ __align__(16) __half g_Bf16[(size_t)W_NUMEL * HIDDEN];  // W2^T fp16 [n][k]
__device__ __align__(16) __half g_W1img[HIDDEN * 136];             // W1^T fp16 image (ROWB layout)
__device__ float g_seg[(size_t)N_NODES * NODE_DIM];
__device__ float g_cnt[N_NODES];

// ---------------- PTX helpers ----------------
__device__ __forceinline__ uint32_t smem_u32(const void* p) {
    uint32_t a;
    asm("{ .reg .u64 t; cvta.to.shared.u64 t, %1; cvt.u32.u64 %0, t; }" : "=r"(a) : "l"(p));
    return a;
}
__device__ __forceinline__ void ldsm_x4(uint32_t* r, uint32_t addr) {
    asm volatile("ldmatrix.sync.aligned.m8n8.x4.shared.b16 {%0,%1,%2,%3}, [%4];"
        : "=r"(r[0]), "=r"(r[1]), "=r"(r[2]), "=r"(r[3]) : "r"(addr));
}
__device__ __forceinline__ void mma_f16(float* c, const uint32_t* a, uint32_t b0, uint32_t b1) {
    asm volatile("mma.sync.aligned.m16n8k16.row.col.f32.f16.f16.f32 "
        "{%0,%1,%2,%3}, {%4,%5,%6,%7}, {%8,%9}, {%0,%1,%2,%3};"
        : "+f"(c[0]), "+f"(c[1]), "+f"(c[2]), "+f"(c[3])
        : "r"(a[0]), "r"(a[1]), "r"(a[2]), "r"(a[3]), "r"(b0), "r"(b1));
}
__device__ __forceinline__ void cp_async16(uint32_t smem_addr, const void* gptr) {
    asm volatile("cp.async.ca.shared.global [%0], [%1], 16;" :: "r"(smem_addr), "l"(gptr));
}
#define CP_COMMIT() asm volatile("cp.async.commit_group;" ::: "memory")
#define CP_WAIT_0() asm volatile("cp.async.wait_group 0;" ::: "memory")

#define ROWB 272

// ---------------- prep: W2^T transpose (320 blocks of 16x64 tiles) + W1 image ----------------
__global__ void prep_kernel(const float* __restrict__ fc_w1,
                            const float* __restrict__ fc_w2) {
    __shared__ float tile[16 * 65];
    const int tid = threadIdx.x;
    const int bid = blockIdx.x;

    if (bid < 320) {
        const int kt = bid / 40;
        const int nt = bid % 40;
#pragma unroll
        for (int it = 0; it < 4; it++) {
            const int i = tid + it * 256;
            const int r = i >> 6, cc = i & 63;
            tile[r * 65 + cc] = fc_w2[(size_t)(kt * 16 + r) * W_NUMEL + nt * 64 + cc];
        }
        __syncthreads();
#pragma unroll
        for (int it = 0; it < 4; it++) {
            const int i = tid + it * 256;
            const int nn = i >> 4, kk = i & 15;
            g_Bf16[(size_t)(nt * 64 + nn) * HIDDEN + kt * 16 + kk] =
                __float2half_rn(tile[kk * 65 + nn]);
        }
    } else {
        for (int i = tid; i < HIDDEN * HIDDEN; i += 256) {
            const int k = i >> 7, n = i & 127;
            g_W1img[n * 136 + k] = __float2half_rn(fc_w1[i]);
        }
    }
}

// ---------------- fused edge kernel: 3 CTAs/SM via SMEM overlay ----------------
// Region0 @0 (34816): prologue attr/h (ROWB rows); steady B ring 2x17408.
// Region1 @34816 (34816): prologue W1 image; steady b2s@34816(10240),
//   x0h@45056(8704), x1h@53760(12800), shs@66560(2048), srcs@68608(512) => 69120.
// EDGE_SMEM = 69632 -> 3 CTAs/SM.
#define OFF_A    0
#define OFF_B    0
#define BBUF     17408
#define OFF_W1   34816
#define OFF_B2   34816
#define OFF_X0H  45056
#define OFF_X1H  53760
#define OFF_SH   66560
#define OFF_SRC  68608
#define EDGE_SMEM 69632

__global__ __launch_bounds__(ETHREADS, 3)
void edge_kernel(const float* __restrict__ node_attr,
                 const float* __restrict__ edge_attr,
                 const float* __restrict__ edge_sh,
                 const float* __restrict__ fc_b1,
                 const float* __restrict__ fc_b2,
                 const int*   __restrict__ edge_index) {
    extern __shared__ char smc[];
    const uint32_t smb = smem_u32(smc);
    __half* x0h = (__half*)(smc + OFF_X0H);
    __half* x1h = (__half*)(smc + OFF_X1H);
    float*  shs = (float*)(smc + OFF_SH);
    int*   srcs = (int*)(smc + OFF_SRC);
    const float* b2s = (const float*)(smc + OFF_B2);

    const int tid  = threadIdx.x;
    const int w    = tid >> 5;          // warp 0..3 -> rows 32w..32w+31
    const int lane = tid & 31;
    const int e0 = blockIdx.x * MTILE;

    const int q2 = 2 * (lane & 3);
    const int r8 = lane >> 2;

    const uint32_t aRowLoc = (uint32_t)((lane & 7) + 8 * ((lane >> 3) & 1));
    const uint32_t aK = (uint32_t)(16 * ((lane >> 4) & 1));
    const uint32_t bRow = (uint32_t)((lane & 7) + 8 * ((lane >> 4) & 1));
    const uint32_t bK = (uint32_t)(16 * ((lane >> 3) & 1));

    // ======== PROLOGUE: h = relu(edge_attr @ W1 + b1), fp16 single-pass ========
    // W1 image -> region1
#pragma unroll
    for (int it = 0; it < 17; it++) {
        const int i = tid + it * ETHREADS;
        if (i < 2176)
            cp_async16(smb + OFF_W1 + (uint32_t)i * 16, (const char*)g_W1img + i * 16);
    }
    CP_COMMIT();

    // attr fp16 -> region0 (own 32 rows per warp)
    {
        const float4* ga = (const float4*)(edge_attr + (size_t)e0 * EDGE_FEAT);
#pragma unroll 4
        for (int r = 0; r < 32; r++) {
            const int row = 32 * w + r;
            const float4 v = ga[(size_t)row * 32 + lane];
            char* dh = smc + OFF_A + row * ROWB + lane * 8;
            *(__half2*)(dh)     = __floats2half2_rn(v.x, v.y);
            *(__half2*)(dh + 4) = __floats2half2_rn(v.z, v.w);
        }
    }
    CP_WAIT_0();          // W1 landed
    __syncthreads();

    // prologue mma (single pass), h -> region0 in place (own rows)
    {
        const uint32_t wB = smb + OFF_W1 + bRow * ROWB + bK;
#pragma unroll
        for (int rt = 0; rt < 2; rt++) {
            const uint32_t aHiB = smb + OFF_A + ((uint32_t)(32 * w + 16 * rt) + aRowLoc) * ROWB + aK;
            float c[16][4];
#pragma unroll
            for (int t = 0; t < 16; t++)
#pragma unroll
                for (int i = 0; i < 4; i++) c[t][i] = 0.0f;
#pragma unroll
            for (int ks = 0; ks < 8; ks++) {
                uint32_t ah[4];
                ldsm_x4(ah, aHiB + ks * 32);
#pragma unroll
                for (int tp = 0; tp < 8; tp++) {
                    uint32_t wf[4];
                    ldsm_x4(wf, wB + tp * (16 * ROWB) + ks * 32);
                    mma_f16(c[2 * tp],     ah, wf[0], wf[1]);
                    mma_f16(c[2 * tp + 1], ah, wf[2], wf[3]);
                }
            }
#pragma unroll
            for (int t = 0; t < 16; t++) {
                const int col = 8 * t + q2;
                const float2 b1v = __ldg((const float2*)(fc_b1 + col));
#pragma unroll
                for (int rr = 0; rr < 2; rr++) {
                    const int mm = 32 * w + 16 * rt + 8 * rr + r8;
                    const float v0 = fmaxf(c[t][2 * rr + 0] + b1v.x, 0.0f);
                    const float v1 = fmaxf(c[t][2 * rr + 1] + b1v.y, 0.0f);
                    *(__half2*)(smc + OFF_A + mm * ROWB + col * 2) =
                        __halves2half2(__float2half_rn(v0), __float2half_rn(v1));
                }
            }
        }
    }
    __syncwarp();

    // A frags -> registers (permanent)
    uint32_t a_[2][8][4];
#pragma unroll
    for (int rt = 0; rt < 2; rt++) {
        const uint32_t base = smb + OFF_A + ((uint32_t)(32 * w + 16 * rt) + aRowLoc) * ROWB + aK;
#pragma unroll
        for (int ks = 0; ks < 8; ks++)
            ldsm_x4(a_[rt][ks], base + ks * 32);
    }
    __syncthreads();      // region0 + region1 dead everywhere

    // B chunk 0 -> stage 0 (region0 reused)
#pragma unroll
    for (int it = 0; it < 8; it++) {
        const int i = tid + it * ETHREADS;
        const int row = i >> 4, kc = i & 15;
        cp_async16(smb + OFF_B + row * ROWB + kc * 16,
                   g_Bf16 + (size_t)row * HIDDEN + kc * 8);
    }
    CP_COMMIT();

    // b2 -> region1 via LDG+STS (visible after first CHUNK_TOP barrier)
#pragma unroll
    for (int it = 0; it < 5; it++) {
        const int i = tid + it * ETHREADS;
        *(float4*)(smc + OFF_B2 + (uint32_t)i * 16) = __ldg((const float4*)(fc_b2 + i * 4));
    }

    // gather per-edge vectors (fp16 tables, region1)
    {
        const int eg  = e0 + tid;
        const int src = edge_index[eg];
        const int dst = edge_index[N_EDGES + eg];
        srcs[tid] = src;
        atomicAdd(&g_cnt[src], 1.0f);
        const float4* na = (const float4*)(node_attr + (size_t)dst * NODE_DIM);
#pragma unroll
        for (int q = 0; q < 8; q++) {
            const float4 v = na[q];
            __half2* p = (__half2*)(x0h + tid * 34 + 4 * q);
            p[0] = __floats2half2_rn(v.x, v.y);
            p[1] = __floats2half2_rn(v.z, v.w);
        }
#pragma unroll
        for (int q = 0; q < 12; q++) {
            const float4 v = na[8 + q];
            __half2* p = (__half2*)(x1h + tid * 50 + 4 * q);
            p[0] = __floats2half2_rn(v.x, v.y);
            p[1] = __floats2half2_rn(v.z, v.w);
        }
        const float4 sh4 = *(const float4*)(edge_sh + (size_t)eg * 4);
        shs[tid * 4 + 0] = sh4.x;
        shs[tid * 4 + 1] = sh4.y;
        shs[tid * 4 + 2] = sh4.z;
        shs[tid * 4 + 3] = sh4.w;
    }

    // ======== STEADY STATE (2-stage ring) ========
    const uint32_t bRowOff = bRow * ROWB + bK;
    int mmr[4];
#pragma unroll
    for (int r = 0; r < 4; r++) mmr[r] = 32 * w + 16 * (r >> 1) + 8 * (r & 1) + r8;

    float sh0r[4], sh1r[4][3];
    bool shLoaded = false;

#define CHUNK_TOP(j) \
    CP_WAIT_0(); \
    __syncthreads(); \
    if ((j) + 1 < NCHUNKS) { \
        const uint32_t sb = smb + OFF_B + (uint32_t)((((j) + 1) & 1) * BBUF); \
        const __half* gp0 = g_Bf16 + (size_t)((j) + 1) * NCHUNK * HIDDEN; \
        _Pragma("unroll") \
        for (int it = 0; it < 8; it++) { \
            const int i = tid + it * ETHREADS; \
            const int row = i >> 4, kc = i & 15; \
            cp_async16(sb + row * ROWB + kc * 16, gp0 + (size_t)row * HIDDEN + kc * 8); \
        } \
        CP_COMMIT(); \
    }

#define LOAD_SH() \
    if (!shLoaded) { \
        _Pragma("unroll") for (int r = 0; r < 4; r++) { \
            sh0r[r] = shs[mmr[r] * 4 + 0]; \
            sh1r[r][0] = shs[mmr[r] * 4 + 1]; \
            sh1r[r][1] = shs[mmr[r] * 4 + 2]; \
            sh1r[r][2] = shs[mmr[r] * 4 + 3]; \
        } \
        shLoaded = true; \
    }

#define CHUNK_MMA_HALF(j, hf, cH) \
    { \
        _Pragma("unroll") for (int rt = 0; rt < 2; rt++) \
        _Pragma("unroll") for (int t = 0; t < 4; t++) \
        _Pragma("unroll") for (int i = 0; i < 4; i++) cH[rt][t][i] = 0.0f; \
        const uint32_t bb = smb + OFF_B + (uint32_t)((((j) & 1)) * BBUF) + bRowOff \
                          + (uint32_t)((hf) * 32 * ROWB); \
        _Pragma("unroll") for (int ks = 0; ks < 8; ks++) { \
            _Pragma("unroll") for (int tp2 = 0; tp2 < 2; tp2++) { \
                uint32_t bf[4]; \
                ldsm_x4(bf, bb + tp2 * (16 * ROWB) + ks * 32); \
                mma_f16(cH[0][2 * tp2],     a_[0][ks], bf[0], bf[1]); \
                mma_f16(cH[0][2 * tp2 + 1], a_[0][ks], bf[2], bf[3]); \
                mma_f16(cH[1][2 * tp2],     a_[1][ks], bf[0], bf[1]); \
                mma_f16(cH[1][2 * tp2 + 1], a_[1][ks], bf[2], bf[3]); \
            } \
        } \
    }

    // ============ phase 1: j 0..23 (block1/block2 -> accO) ============
    {
        float accO[4][8];
#pragma unroll
        for (int r = 0; r < 4; r++)
#pragma unroll
            for (int i = 0; i < 8; i++) accO[r][i] = 0.0f;

#define EPI1(gv, cH) { \
        const int g = (gv); \
        float s[4]; \
        if (g < 32) { \
            _Pragma("unroll") for (int r = 0; r < 4; r++) \
                s[r] = C0f * sh0r[r] * __half2float(x0h[mmr[r] * 34 + g]); \
        } else { \
            const int u = g - 32; \
            _Pragma("unroll") for (int r = 0; r < 4; r++) \
                s[r] = C0IS3 * (__half2float(x1h[mmr[r] * 50 + 3 * u])     * sh1r[r][0] \
                              + __half2float(x1h[mmr[r] * 50 + 3 * u + 1]) * sh1r[r][1] \
                              + __half2float(x1h[mmr[r] * 50 + 3 * u + 2]) * sh1r[r][2]); \
        } \
        _Pragma("unroll") for (int tt = 0; tt < 4; tt++) { \
            const float2 bv = *(const float2*)(b2s + 32 * g + 8 * tt + q2); \
            _Pragma("unroll") for (int rt = 0; rt < 2; rt++) \
            _Pragma("unroll") for (int rr = 0; rr < 2; rr++) { \
                const int r = 2 * rt + rr; \
                accO[r][2 * tt]     += s[r] * (cH[rt][tt][2 * rr]     + bv.x); \
                accO[r][2 * tt + 1] += s[r] * (cH[rt][tt][2 * rr + 1] + bv.y); \
            } \
        } \
    }

        for (int j = 0; j < 24; j++) {
            CHUNK_TOP(j);
            LOAD_SH();
            float cH[2][4][4];
            CHUNK_MMA_HALF(j, 0, cH);
            EPI1(2 * j, cH);
            CHUNK_MMA_HALF(j, 1, cH);
            EPI1(2 * j + 1, cH);
        }
#pragma unroll
        for (int r = 0; r < 4; r++) {
            float* segp = g_seg + (size_t)srcs[mmr[r]] * NODE_DIM;
#pragma unroll
            for (int tt = 0; tt < 4; tt++)
#pragma unroll
                for (int b = 0; b < 2; b++)
                    atomicAdd(segp + 8 * tt + q2 + b, accO[r][2 * tt + b]);
        }
    }

    // ============ phase 2: j 24..31 (block3 -> t3) ============
    {
        float accT3[4][4];
#pragma unroll
        for (int r = 0; r < 4; r++)
#pragma unroll
            for (int i = 0; i < 4; i++) accT3[r][i] = 0.0f;

#define EPI2(gv, cH) { \
        const int g = (gv); \
        const int u0 = 2 * (g - 48); \
        float s[4][2]; \
        _Pragma("unroll") for (int r = 0; r < 4; r++) { \
            s[r][0] = C1IS3 * __half2float(x0h[mmr[r] * 34 + u0]); \
            s[r][1] = C1IS3 * __half2float(x0h[mmr[r] * 34 + u0 + 1]); \
        } \
        _Pragma("unroll") for (int tt = 0; tt < 4; tt++) { \
            const int us = tt >> 1; \
            const int sl = 2 * (tt & 1); \
            const float2 bv = *(const float2*)(b2s + 32 * g + 8 * tt + q2); \
            _Pragma("unroll") for (int rt = 0; rt < 2; rt++) \
            _Pragma("unroll") for (int rr = 0; rr < 2; rr++) { \
                const int r = 2 * rt + rr; \
                accT3[r][sl]     += s[r][us] * (cH[rt][tt][2 * rr]     + bv.x); \
                accT3[r][sl + 1] += s[r][us] * (cH[rt][tt][2 * rr + 1] + bv.y); \
            } \
        } \
    }

        for (int j = 24; j < 32; j++) {
            CHUNK_TOP(j);
            float cH[2][4][4];
            CHUNK_MMA_HALF(j, 0, cH);
            EPI2(2 * j, cH);
            CHUNK_MMA_HALF(j, 1, cH);
            EPI2(2 * j + 1, cH);
        }
#pragma unroll
        for (int r = 0; r < 4; r++) {
            float* segp = g_seg + (size_t)srcs[mmr[r]] * NODE_DIM;
#pragma unroll
            for (int ws = 0; ws < 2; ws++)
#pragma unroll
                for (int b = 0; b < 2; b++) {
                    const int wc = 8 * ws + q2 + b;
                    const float t3 = accT3[r][2 * ws + b];
                    atomicAdd(segp + 32 + 3 * wc + 0, sh1r[r][0] * t3);
                    atomicAdd(segp + 32 + 3 * wc + 1, sh1r[r][1] * t3);
                    atomicAdd(segp + 32 + 3 * wc + 2, sh1r[r][2] * t3);
                }
        }
    }

    // ============ phase 3: j 32..39 (block4/5 -> V) ============
    {
        float accV[4][4][3];
#pragma unroll
        for (int r = 0; r < 4; r++)
#pragma unroll
            for (int i = 0; i < 4; i++)
#pragma unroll
                for (int k = 0; k < 3; k++) accV[r][i][k] = 0.0f;

#define EPI3(gv, cH) { \
        const int g = (gv); \
        const bool is5 = (g >= 72); \
        const int u0 = is5 ? 2 * (g - 72) : 2 * (g - 64); \
        float av[4][2][3]; \
        _Pragma("unroll") for (int r = 0; r < 4; r++) { \
            _Pragma("unroll") for (int us = 0; us < 2; us++) { \
                const int u = u0 + us; \
                const float xx = __half2float(x1h[mmr[r] * 50 + 3 * u + 0]); \
                const float xy = __half2float(x1h[mmr[r] * 50 + 3 * u + 1]); \
                const float xz = __half2float(x1h[mmr[r] * 50 + 3 * u + 2]); \
                if (!is5) { \
                    const float kb = C1IS3 * sh0r[r]; \
                    av[r][us][0] = kb * xx; \
                    av[r][us][1] = kb * xy; \
                    av[r][us][2] = kb * xz; \
                } else { \
                    av[r][us][0] = C1IS6 * (xy * sh1r[r][2] - xz * sh1r[r][1]); \
                    av[r][us][1] = C1IS6 * (xz * sh1r[r][0] - xx * sh1r[r][2]); \
                    av[r][us][2] = C1IS6 * (xx * sh1r[r][1] - xy * sh1r[r][0]); \
                } \
            } \
        } \
        _Pragma("unroll") for (int tt = 0; tt < 4; tt++) { \
            const int us = tt >> 1; \
            const int sl = 2 * (tt & 1); \
            const float2 bv = *(const float2*)(b2s + 32 * g + 8 * tt + q2); \
            _Pragma("unroll") for (int rt = 0; rt < 2; rt++) \
            _Pragma("unroll") for (int rr = 0; rr < 2; rr++) { \
                const int r = 2 * rt + rr; \
                const float D0 = cH[rt][tt][2 * rr]     + bv.x; \
                const float D1 = cH[rt][tt][2 * rr + 1] + bv.y; \
                _Pragma("unroll") for (int k = 0; k < 3; k++) { \
                    accV[r][sl][k]     += av[r][us][k] * D0; \
                    accV[r][sl + 1][k] += av[r][us][k] * D1; \
                } \
            } \
        } \
    }

        for (int j = 32; j < 40; j++) {
            CHUNK_TOP(j);
            float cH[2][4][4];
            CHUNK_MMA_HALF(j, 0, cH);
            EPI3(2 * j, cH);
            CHUNK_MMA_HALF(j, 1, cH);
            EPI3(2 * j + 1, cH);
        }
#pragma unroll
        for (int r = 0; r < 4; r++) {
            float* segp = g_seg + (size_t)srcs[mmr[r]] * NODE_DIM;
#pragma unroll
            for (int ws = 0; ws < 2; ws++)
#pragma unroll
                for (int b = 0; b < 2; b++) {
                    const int wc = 8 * ws + q2 + b;
#pragma unroll
                    for (int k = 0; k < 3; k++)
                        atomicAdd(segp + 32 + 3 * wc + k, accV[r][2 * ws + b][k]);
                }
        }
    }
}

// ---------------- node epilogue ----------------
__global__ void node_kernel(const float* __restrict__ node_attr,
                            const float* __restrict__ mean_shift,
                            const float* __restrict__ aw,
                            const float* __restrict__ ab,
                            float* __restrict__ out) {
    const int warp = (blockIdx.x * blockDim.x + threadIdx.x) >> 5;
    const int lane = threadIdx.x & 31;
    if (warp >= N_NODES) return;
    const unsigned full = 0xFFFFFFFFu;

    const float inv = 1.0f / fmaxf(g_cnt[warp], 1.0f);
    const float* seg = g_seg + (size_t)warp * NODE_DIM;
    const float* na  = node_attr + (size_t)warp * NODE_DIM;

    float o0 = seg[lane] * inv + na[lane];
    float mval = o0;
#pragma unroll
    for (int off = 16; off; off >>= 1) mval += __shfl_xor_sync(full, mval, off);
    mval *= (1.0f / 32.0f);
    const float f0 = o0 - mval * mean_shift[lane];
    float s = f0 * f0;
#pragma unroll
    for (int off = 16; off; off >>= 1) s += __shfl_xor_sync(full, s, off);
    const float sc0 = rsqrtf(s * (1.0f / 32.0f) + EPS_LN) * aw[lane];
    out[(size_t)warp * NODE_DIM + lane] = f0 * sc0 + ab[lane];

    float vx = 0.0f, vy = 0.0f, vz = 0.0f, msv = 0.0f;
    if (lane < 16) {
        vx = seg[32 + 3 * lane + 0] * inv + na[32 + 3 * lane + 0];
        vy = seg[32 + 3 * lane + 1] * inv + na[32 + 3 * lane + 1];
        vz = seg[32 + 3 * lane + 2] * inv + na[32 + 3 * lane + 2];
        msv = mean_shift[32 + lane];
    }
    float mx = vx, my = vy, mz = vz;
#pragma unroll
    for (int off = 16; off; off >>= 1) {
        mx += __shfl_xor_sync(full, mx, off);
        my += __shfl_xor_sync(full, my, off);
        mz += __shfl_xor_sync(full, mz, off);
    }
    mx *= (1.0f / 16.0f); my *= (1.0f / 16.0f); mz *= (1.0f / 16.0f);
    const float fx = vx - mx * msv;
    const float fy = vy - my * msv;
    const float fz = vz - mz * msv;
    float sq = (lane < 16) ? (fx * fx + fy * fy + fz * fz) : 0.0f;
#pragma unroll
    for (int off = 16; off; off >>= 1) sq += __shfl_xor_sync(full, sq, off);
    if (lane < 16) {
        const float sc1 = rsqrtf(sq * (1.0f / 48.0f) + EPS_LN) * aw[32 + lane];
        out[(size_t)warp * NODE_DIM + 32 + 3 * lane + 0] = fx * sc1;
        out[(size_t)warp * NODE_DIM + 32 + 3 * lane + 1] = fy * sc1;
        out[(size_t)warp * NODE_DIM + 32 + 3 * lane + 2] = fz * sc1;
    }
}

// ---------------- launch ----------------
extern "C" void kernel_launch(void* const* d_in, const int* in_sizes, int n_in,
                              void* d_out, int out_size) {
    const float* node_attr  = (const float*)d_in[0];
    const float* edge_attr  = (const float*)d_in[1];
    const float* edge_sh    = (const float*)d_in[2];
    const float* fc_w1      = (const float*)d_in[3];
    const float* fc_b1      = (const float*)d_in[4];
    const float* fc_w2      = (const float*)d_in[5];
    const float* fc_b2      = (const float*)d_in[6];
    const float* mean_shift = (const float*)d_in[7];
    const float* aw         = (const float*)d_in[8];
    const float* ab         = (const float*)d_in[9];
    const int*   edge_index = (const int*)d_in[10];
    float* out = (float*)d_out;

    cudaFuncSetAttribute(edge_kernel, cudaFuncAttributeMaxDynamicSharedMemorySize, (int)EDGE_SMEM);

    void* seg_ptr = nullptr;
    void* cnt_ptr = nullptr;
    cudaGetSymbolAddress(&seg_ptr, g_seg);
    cudaGetSymbolAddress(&cnt_ptr, g_cnt);
    cudaMemsetAsync(seg_ptr, 0, sizeof(float) * (size_t)N_NODES * NODE_DIM);
    cudaMemsetAsync(cnt_ptr, 0, sizeof(float) * N_NODES);

    prep_kernel<<<321, 256>>>(fc_w1, fc_w2);
    edge_kernel<<<NTILES, ETHREADS, EDGE_SMEM>>>(node_attr, edge_attr, edge_sh, fc_b1, fc_b2, edge_index);
    node_kernel<<<(N_NODES * 32 + 255) / 256, 256>>>(node_attr, mean_shift, aw, ab, out);
}

// round 17
// speedup vs baseline: 1.1974x; 1.1974x over previous
#include <cuda_runtime.h>
#include <cuda_fp16.h>
#include <cstdint>
#include <cstddef>

#define N_NODES 20000
#define N_EDGES 160000
#define MUL0 32
#define MUL1 16
#define NODE_DIM 80
#define EDGE_FEAT 128
#define HIDDEN 128
#define W_NUMEL 2560
#define MTILE 128
#define NTILES (N_EDGES / MTILE)      // 1250
#define NCHUNK 64
#define NCHUNKS (W_NUMEL / NCHUNK)    // 40
#define ETHREADS 128

#define C0f   0.14433756729740643f
#define C1f   0.21650635094610965f
#define IS3f  0.5773502691896258f
#define IS6f  0.40824829046386296f
#define C0IS3 (C0f * IS3f)
#define C1IS3 (C1f * IS3f)
#define C1IS6 (C1f * IS6f)
#define EPS_LN 1e-5f

// ---------------- device scratch ----------------
__device__ __align__(16) __half g_Bf16[(size_t)HIDDEN * W_NUMEL];  // W2 fp16 K-MAJOR [k][n] (same order as fc_w2)
__device__ __align__(16) __half g_W1img[HIDDEN * 136];             // W1^T fp16 image (ROWB [n][k] layout)
__device__ float g_seg[(size_t)N_NODES * NODE_DIM];
__device__ float g_cnt[N_NODES];

// ---------------- PTX helpers ----------------
__device__ __forceinline__ uint32_t smem_u32(const void* p) {
    uint32_t a;
    asm("{ .reg .u64 t; cvta.to.shared.u64 t, %1; cvt.u32.u64 %0, t; }" : "=r"(a) : "l"(p));
    return a;
}
__device__ __forceinline__ void ldsm_x4(uint32_t* r, uint32_t addr) {
    asm volatile("ldmatrix.sync.aligned.m8n8.x4.shared.b16 {%0,%1,%2,%3}, [%4];"
        : "=r"(r[0]), "=r"(r[1]), "=r"(r[2]), "=r"(r[3]) : "r"(addr));
}
__device__ __forceinline__ void ldsm_x4_t(uint32_t* r, uint32_t addr) {
    asm volatile("ldmatrix.sync.aligned.m8n8.x4.trans.shared.b16 {%0,%1,%2,%3}, [%4];"
        : "=r"(r[0]), "=r"(r[1]), "=r"(r[2]), "=r"(r[3]) : "r"(addr));
}
__device__ __forceinline__ void mma_f16(float* c, const uint32_t* a, uint32_t b0, uint32_t b1) {
    asm volatile("mma.sync.aligned.m16n8k16.row.col.f32.f16.f16.f32 "
        "{%0,%1,%2,%3}, {%4,%5,%6,%7}, {%8,%9}, {%0,%1,%2,%3};"
        : "+f"(c[0]), "+f"(c[1]), "+f"(c[2]), "+f"(c[3])
        : "r"(a[0]), "r"(a[1]), "r"(a[2]), "r"(a[3]), "r"(b0), "r"(b1));
}
__device__ __forceinline__ void cp_async16(uint32_t smem_addr, const void* gptr) {
    asm volatile("cp.async.ca.shared.global [%0], [%1], 16;" :: "r"(smem_addr), "l"(gptr));
}
#define CP_COMMIT() asm volatile("cp.async.commit_group;" ::: "memory")
#define CP_WAIT_0() asm volatile("cp.async.wait_group 0;" ::: "memory")
#define CP_WAIT_1() asm volatile("cp.async.wait_group 1;" ::: "memory")

#define ROWB 272     // [n][k] image row stride (A/h, W1)
#define ROWK 144     // [k][n] B-chunk row stride (64 halves + pad)

// ---------------- prep: coalesced fp32->fp16 copy of fc_w2 (no transpose!) + W1 image ----------------
__global__ void prep_kernel(const float* __restrict__ fc_w1,
                            const float* __restrict__ fc_w2) {
    const int tid = threadIdx.x;
    const int bid = blockIdx.x;
    if (bid < 160) {
        const int i = bid * 256 + tid;          // 0..40959, each = 8 elems
        const float4 a = ((const float4*)fc_w2)[2 * i];
        const float4 b = ((const float4*)fc_w2)[2 * i + 1];
        const __half2 h0 = __floats2half2_rn(a.x, a.y);
        const __half2 h1 = __floats2half2_rn(a.z, a.w);
        const __half2 h2 = __floats2half2_rn(b.x, b.y);
        const __half2 h3 = __floats2half2_rn(b.z, b.w);
        int4 o;
        o.x = *(const int*)&h0; o.y = *(const int*)&h1;
        o.z = *(const int*)&h2; o.w = *(const int*)&h3;
        ((int4*)g_Bf16)[i] = o;
    } else {
        for (int i = tid; i < HIDDEN * HIDDEN; i += 256) {
            const int k = i >> 7, n = i & 127;
            g_W1img[n * 136 + k] = __float2half_rn(fc_w1[i]);
        }
    }
}

// ---------------- fused edge kernel ----------------
// B ring @0: 3 stages x 18432 ([k=128][ROWK=144]) = 55296.
//   Prologue attr/h image ([128][272] = 34816) overlays [0,34816) (stages 0/1 area).
// W1 image @55296 (34816, prologue only). Steady tables overlay it:
//   b2s@55296(10240), x0h@65536(8704), x1h@74240(12800), shs@87040(2048), srcs@89088(512).
// EDGE_SMEM = 90112 -> 2 CTAs/SM.
#define OFF_A    0
#define OFF_B    0
#define BBUF     18432
#define OFF_W1   55296
#define OFF_B2   55296
#define OFF_X0H  65536
#define OFF_X1H  74240
#define OFF_SH   87040
#define OFF_SRC  89088
#define EDGE_SMEM 90112

__global__ __launch_bounds__(ETHREADS, 2)
void edge_kernel(const float* __restrict__ node_attr,
                 const float* __restrict__ edge_attr,
                 const float* __restrict__ edge_sh,
                 const float* __restrict__ fc_b1,
                 const float* __restrict__ fc_b2,
                 const int*   __restrict__ edge_index) {
    extern __shared__ char smc[];
    const uint32_t smb = smem_u32(smc);
    __half* x0h = (__half*)(smc + OFF_X0H);
    __half* x1h = (__half*)(smc + OFF_X1H);
    float*  shs = (float*)(smc + OFF_SH);
    int*   srcs = (int*)(smc + OFF_SRC);
    const float* b2s = (const float*)(smc + OFF_B2);

    const int tid  = threadIdx.x;
    const int w    = tid >> 5;          // warp 0..3 -> rows 32w..32w+31
    const int lane = tid & 31;
    const int e0 = blockIdx.x * MTILE;

    const int q2 = 2 * (lane & 3);
    const int r8 = lane >> 2;

    // [n][k] image lane mapping (A frags, W1)
    const uint32_t aRowLoc = (uint32_t)((lane & 7) + 8 * ((lane >> 3) & 1));
    const uint32_t aK = (uint32_t)(16 * ((lane >> 4) & 1));
    const uint32_t wRow = (uint32_t)((lane & 7) + 8 * ((lane >> 4) & 1));
    const uint32_t wK = (uint32_t)(16 * ((lane >> 3) & 1));
    // [k][n] trans lane mapping (B chunks): k row within 16-tile + n-half byte offset
    const uint32_t bKRow = (uint32_t)((lane & 7) + 8 * ((lane >> 3) & 1));
    const uint32_t bNOff = (uint32_t)(16 * ((lane >> 4) & 1));

    // ======== PROLOGUE: h = relu(edge_attr @ W1 + b1), fp16 single-pass ========
#pragma unroll
    for (int it = 0; it < 17; it++) {
        const int i = tid + it * ETHREADS;
        if (i < 2176)
            cp_async16(smb + OFF_W1 + (uint32_t)i * 16, (const char*)g_W1img + i * 16);
    }
    CP_COMMIT();

    // attr fp16 -> region A (own 32 rows per warp)
    {
        const float4* ga = (const float4*)(edge_attr + (size_t)e0 * EDGE_FEAT);
#pragma unroll 4
        for (int r = 0; r < 32; r++) {
            const int row = 32 * w + r;
            const float4 v = ga[(size_t)row * 32 + lane];
            char* dh = smc + OFF_A + row * ROWB + lane * 8;
            *(__half2*)(dh)     = __floats2half2_rn(v.x, v.y);
            *(__half2*)(dh + 4) = __floats2half2_rn(v.z, v.w);
        }
    }
    CP_WAIT_0();          // W1 landed
    __syncthreads();

    // prologue mma (single pass), h -> region A in place (own rows)
    {
        const uint32_t wB = smb + OFF_W1 + wRow * ROWB + wK;
#pragma unroll
        for (int rt = 0; rt < 2; rt++) {
            const uint32_t aHiB = smb + OFF_A + ((uint32_t)(32 * w + 16 * rt) + aRowLoc) * ROWB + aK;
            float c[16][4];
#pragma unroll
            for (int t = 0; t < 16; t++)
#pragma unroll
                for (int i = 0; i < 4; i++) c[t][i] = 0.0f;
#pragma unroll
            for (int ks = 0; ks < 8; ks++) {
                uint32_t ah[4];
                ldsm_x4(ah, aHiB + ks * 32);
#pragma unroll
                for (int tp = 0; tp < 8; tp++) {
                    uint32_t wf[4];
                    ldsm_x4(wf, wB + tp * (16 * ROWB) + ks * 32);
                    mma_f16(c[2 * tp],     ah, wf[0], wf[1]);
                    mma_f16(c[2 * tp + 1], ah, wf[2], wf[3]);
                }
            }
#pragma unroll
            for (int t = 0; t < 16; t++) {
                const int col = 8 * t + q2;
                const float2 b1v = __ldg((const float2*)(fc_b1 + col));
#pragma unroll
                for (int rr = 0; rr < 2; rr++) {
                    const int mm = 32 * w + 16 * rt + 8 * rr + r8;
                    const float v0 = fmaxf(c[t][2 * rr + 0] + b1v.x, 0.0f);
                    const float v1 = fmaxf(c[t][2 * rr + 1] + b1v.y, 0.0f);
                    *(__half2*)(smc + OFF_A + mm * ROWB + col * 2) =
                        __halves2half2(__float2half_rn(v0), __float2half_rn(v1));
                }
            }
        }
    }
    __syncwarp();

    // A frags -> registers (permanent)
    uint32_t a_[2][8][4];
#pragma unroll
    for (int rt = 0; rt < 2; rt++) {
        const uint32_t base = smb + OFF_A + ((uint32_t)(32 * w + 16 * rt) + aRowLoc) * ROWB + aK;
#pragma unroll
        for (int ks = 0; ks < 8; ks++)
            ldsm_x4(a_[rt][ks], base + ks * 32);
    }
    __syncthreads();      // A region + W1 region dead everywhere

    // B chunk 0 -> stage 0, B chunk 1 -> stage 1 (separate groups)
#pragma unroll
    for (int it = 0; it < 8; it++) {
        const int i = tid + it * ETHREADS;       // 0..1023 = k(128) x kc(8)
        const int row = i >> 3, kc = i & 7;
        cp_async16(smb + OFF_B + row * ROWK + kc * 16,
                   g_Bf16 + (size_t)row * W_NUMEL + kc * 8);
    }
    CP_COMMIT();
#pragma unroll
    for (int it = 0; it < 8; it++) {
        const int i = tid + it * ETHREADS;
        const int row = i >> 3, kc = i & 7;
        cp_async16(smb + OFF_B + BBUF + row * ROWK + kc * 16,
                   g_Bf16 + (size_t)row * W_NUMEL + NCHUNK + kc * 8);
    }
    CP_COMMIT();

    // b2 -> SMEM (dead W1 region)
#pragma unroll
    for (int it = 0; it < 5; it++) {
        const int i = tid + it * ETHREADS;
        *(float4*)(smc + OFF_B2 + (uint32_t)i * 16) = __ldg((const float4*)(fc_b2 + i * 4));
    }

    // gather per-edge vectors (fp16 tables, dead W1 region)
    {
        const int eg  = e0 + tid;
        const int src = edge_index[eg];
        const int dst = edge_index[N_EDGES + eg];
        srcs[tid] = src;
        atomicAdd(&g_cnt[src], 1.0f);
        const float4* na = (const float4*)(node_attr + (size_t)dst * NODE_DIM);
#pragma unroll
        for (int q = 0; q < 8; q++) {
            const float4 v = na[q];
            __half2* p = (__half2*)(x0h + tid * 34 + 4 * q);
            p[0] = __floats2half2_rn(v.x, v.y);
            p[1] = __floats2half2_rn(v.z, v.w);
        }
#pragma unroll
        for (int q = 0; q < 12; q++) {
            const float4 v = na[8 + q];
            __half2* p = (__half2*)(x1h + tid * 50 + 4 * q);
            p[0] = __floats2half2_rn(v.x, v.y);
            p[1] = __floats2half2_rn(v.z, v.w);
        }
        const float4 sh4 = *(const float4*)(edge_sh + (size_t)eg * 4);
        shs[tid * 4 + 0] = sh4.x;
        shs[tid * 4 + 1] = sh4.y;
        shs[tid * 4 + 2] = sh4.z;
        shs[tid * 4 + 3] = sh4.w;
    }

    // ======== STEADY STATE: 3-stage ring, trans B loads ========
    const uint32_t bOff = bKRow * ROWK + bNOff;
    int mmr[4];
#pragma unroll
    for (int r = 0; r < 4; r++) mmr[r] = 32 * w + 16 * (r >> 1) + 8 * (r & 1) + r8;

    float sh0r[4], sh1r[4][3];
    bool shLoaded = false;

#define CHUNK_TOP(j) \
    if ((j) + 1 < NCHUNKS) { CP_WAIT_1(); } else { CP_WAIT_0(); } \
    __syncthreads(); \
    if ((j) + 2 < NCHUNKS) { \
        const uint32_t sb = smb + OFF_B + (uint32_t)((((j) + 2) % 3) * BBUF); \
        const __half* gp0 = g_Bf16 + (size_t)((j) + 2) * NCHUNK; \
        _Pragma("unroll") \
        for (int it = 0; it < 8; it++) { \
            const int i = tid + it * ETHREADS; \
            const int row = i >> 3, kc = i & 7; \
            cp_async16(sb + row * ROWK + kc * 16, gp0 + (size_t)row * W_NUMEL + kc * 8); \
        } \
        CP_COMMIT(); \
    }

#define LOAD_SH() \
    if (!shLoaded) { \
        _Pragma("unroll") for (int r = 0; r < 4; r++) { \
            sh0r[r] = shs[mmr[r] * 4 + 0]; \
            sh1r[r][0] = shs[mmr[r] * 4 + 1]; \
            sh1r[r][1] = shs[mmr[r] * 4 + 2]; \
            sh1r[r][2] = shs[mmr[r] * 4 + 3]; \
        } \
        shLoaded = true; \
    }

// full-chunk MMA: B from k-major stage via ldmatrix.trans
#define CHUNK_MMA(j) \
    float c2[2][8][4]; \
    { \
        _Pragma("unroll") for (int rt = 0; rt < 2; rt++) \
        _Pragma("unroll") for (int t = 0; t < 8; t++) \
        _Pragma("unroll") for (int i = 0; i < 4; i++) c2[rt][t][i] = 0.0f; \
        const uint32_t bb = smb + OFF_B + (uint32_t)(((j) % 3) * BBUF) + bOff; \
        _Pragma("unroll") for (int ks = 0; ks < 8; ks++) { \
            _Pragma("unroll") for (int tp = 0; tp < 4; tp++) { \
                uint32_t bf[4]; \
                ldsm_x4_t(bf, bb + (uint32_t)(ks * 16 * ROWK) + (uint32_t)(tp * 32)); \
                mma_f16(c2[0][2 * tp],     a_[0][ks], bf[0], bf[1]); \
                mma_f16(c2[0][2 * tp + 1], a_[0][ks], bf[2], bf[3]); \
                mma_f16(c2[1][2 * tp],     a_[1][ks], bf[0], bf[1]); \
                mma_f16(c2[1][2 * tp + 1], a_[1][ks], bf[2], bf[3]); \
            } \
        } \
    }

    // ============ phase 1: j 0..23 (block1/block2 -> accO) ============
    {
        float accO[4][8];
#pragma unroll
        for (int r = 0; r < 4; r++)
#pragma unroll
            for (int i = 0; i < 8; i++) accO[r][i] = 0.0f;

        for (int j = 0; j < 24; j++) {
            CHUNK_TOP(j);
            LOAD_SH();
            CHUNK_MMA(j);
#pragma unroll
            for (int gi = 0; gi < 2; gi++) {
                const int g = 2 * j + gi;
                float s[4];
                if (g < 32) {
#pragma unroll
                    for (int r = 0; r < 4; r++)
                        s[r] = C0f * sh0r[r] * __half2float(x0h[mmr[r] * 34 + g]);
                } else {
                    const int u = g - 32;
#pragma unroll
                    for (int r = 0; r < 4; r++)
                        s[r] = C0IS3 * (__half2float(x1h[mmr[r] * 50 + 3 * u])     * sh1r[r][0]
                                      + __half2float(x1h[mmr[r] * 50 + 3 * u + 1]) * sh1r[r][1]
                                      + __half2float(x1h[mmr[r] * 50 + 3 * u + 2]) * sh1r[r][2]);
                }
#pragma unroll
                for (int tt = 0; tt < 4; tt++) {
                    const float2 bv = *(const float2*)(b2s + 32 * g + 8 * tt + q2);
#pragma unroll
                    for (int rt = 0; rt < 2; rt++)
#pragma unroll
                        for (int rr = 0; rr < 2; rr++) {
                            const int r = 2 * rt + rr;
                            float* cc = c2[rt][4 * gi + tt];
                            accO[r][2 * tt]     += s[r] * (cc[2 * rr]     + bv.x);
                            accO[r][2 * tt + 1] += s[r] * (cc[2 * rr + 1] + bv.y);
                        }
                }
            }
        }
#pragma unroll
        for (int r = 0; r < 4; r++) {
            float* segp = g_seg + (size_t)srcs[mmr[r]] * NODE_DIM;
#pragma unroll
            for (int tt = 0; tt < 4; tt++)
#pragma unroll
                for (int b = 0; b < 2; b++)
                    atomicAdd(segp + 8 * tt + q2 + b, accO[r][2 * tt + b]);
        }
    }

    // ============ phase 2: j 24..31 (block3 -> t3) ============
    {
        float accT3[4][4];
#pragma unroll
        for (int r = 0; r < 4; r++)
#pragma unroll
            for (int i = 0; i < 4; i++) accT3[r][i] = 0.0f;

        for (int j = 24; j < 32; j++) {
            CHUNK_TOP(j);
            CHUNK_MMA(j);
#pragma unroll
            for (int gi = 0; gi < 2; gi++) {
                const int g = 2 * j + gi;
                const int u0 = 2 * (g - 48);
                float s[4][2];
#pragma unroll
                for (int r = 0; r < 4; r++) {
                    s[r][0] = C1IS3 * __half2float(x0h[mmr[r] * 34 + u0]);
                    s[r][1] = C1IS3 * __half2float(x0h[mmr[r] * 34 + u0 + 1]);
                }
#pragma unroll
                for (int tt = 0; tt < 4; tt++) {
                    const int us = tt >> 1;
                    const int sl = 2 * (tt & 1);
                    const float2 bv = *(const float2*)(b2s + 32 * g + 8 * tt + q2);
#pragma unroll
                    for (int rt = 0; rt < 2; rt++)
#pragma unroll
                        for (int rr = 0; rr < 2; rr++) {
                            const int r = 2 * rt + rr;
                            float* cc = c2[rt][4 * gi + tt];
                            accT3[r][sl]     += s[r][us] * (cc[2 * rr]     + bv.x);
                            accT3[r][sl + 1] += s[r][us] * (cc[2 * rr + 1] + bv.y);
                        }
                }
            }
        }
#pragma unroll
        for (int r = 0; r < 4; r++) {
            float* segp = g_seg + (size_t)srcs[mmr[r]] * NODE_DIM;
#pragma unroll
            for (int ws = 0; ws < 2; ws++)
#pragma unroll
                for (int b = 0; b < 2; b++) {
                    const int wc = 8 * ws + q2 + b;
                    const float t3 = accT3[r][2 * ws + b];
                    atomicAdd(segp + 32 + 3 * wc + 0, sh1r[r][0] * t3);
                    atomicAdd(segp + 32 + 3 * wc + 1, sh1r[r][1] * t3);
                    atomicAdd(segp + 32 + 3 * wc + 2, sh1r[r][2] * t3);
                }
        }
    }

    // ============ phase 3: j 32..39 (block4/5 -> V) ============
    {
        float accV[4][4][3];
#pragma unroll
        for (int r = 0; r < 4; r++)
#pragma unroll
            for (int i = 0; i < 4; i++)
#pragma unroll
                for (int k = 0; k < 3; k++) accV[r][i][k] = 0.0f;

        for (int j = 32; j < 40; j++) {
            CHUNK_TOP(j);
            CHUNK_MMA(j);
#pragma unroll
            for (int gi = 0; gi < 2; gi++) {
                const int g = 2 * j + gi;
                const bool is5 = (g >= 72);
                const int u0 = is5 ? 2 * (g - 72) : 2 * (g - 64);
                float av[4][2][3];
#pragma unroll
                for (int r = 0; r < 4; r++) {
#pragma unroll
                    for (int us = 0; us < 2; us++) {
                        const int u = u0 + us;
                        const float xx = __half2float(x1h[mmr[r] * 50 + 3 * u + 0]);
                        const float xy = __half2float(x1h[mmr[r] * 50 + 3 * u + 1]);
                        const float xz = __half2float(x1h[mmr[r] * 50 + 3 * u + 2]);
                        if (!is5) {
                            const float kb = C1IS3 * sh0r[r];
                            av[r][us][0] = kb * xx;
                            av[r][us][1] = kb * xy;
                            av[r][us][2] = kb * xz;
                        } else {
                            av[r][us][0] = C1IS6 * (xy * sh1r[r][2] - xz * sh1r[r][1]);
                            av[r][us][1] = C1IS6 * (xz * sh1r[r][0] - xx * sh1r[r][2]);
                            av[r][us][2] = C1IS6 * (xx * sh1r[r][1] - xy * sh1r[r][0]);
                        }
                    }
                }
#pragma unroll
                for (int tt = 0; tt < 4; tt++) {
                    const int us = tt >> 1;
                    const int sl = 2 * (tt & 1);
                    const float2 bv = *(const float2*)(b2s + 32 * g + 8 * tt + q2);
#pragma unroll
                    for (int rt = 0; rt < 2; rt++)
#pragma unroll
                        for (int rr = 0; rr < 2; rr++) {
                            const int r = 2 * rt + rr;
                            float* cc = c2[rt][4 * gi + tt];
                            const float D0 = cc[2 * rr] + bv.x;
                            const float D1 = cc[2 * rr + 1] + bv.y;
#pragma unroll
                            for (int k = 0; k < 3; k++) {
                                accV[r][sl][k]     += av[r][us][k] * D0;
                                accV[r][sl + 1][k] += av[r][us][k] * D1;
                            }
                        }
                }
            }
        }
#pragma unroll
        for (int r = 0; r < 4; r++) {
            float* segp = g_seg + (size_t)srcs[mmr[r]] * NODE_DIM;
#pragma unroll
            for (int ws = 0; ws < 2; ws++)
#pragma unroll
                for (int b = 0; b < 2; b++) {
                    const int wc = 8 * ws + q2 + b;
#pragma unroll
                    for (int k = 0; k < 3; k++)
                        atomicAdd(segp + 32 + 3 * wc + k, accV[r][2 * ws + b][k]);
                }
        }
    }
}

// ---------------- node epilogue ----------------
__global__ void node_kernel(const float* __restrict__ node_attr,
                            const float* __restrict__ mean_shift,
                            const float* __restrict__ aw,
                            const float* __restrict__ ab,
                            float* __restrict__ out) {
    const int warp = (blockIdx.x * blockDim.x + threadIdx.x) >> 5;
    const int lane = threadIdx.x & 31;
    if (warp >= N_NODES) return;
    const unsigned full = 0xFFFFFFFFu;

    const float inv = 1.0f / fmaxf(g_cnt[warp], 1.0f);
    const float* seg = g_seg + (size_t)warp * NODE_DIM;
    const float* na  = node_attr + (size_t)warp * NODE_DIM;

    float o0 = seg[lane] * inv + na[lane];
    float mval = o0;
#pragma unroll
    for (int off = 16; off; off >>= 1) mval += __shfl_xor_sync(full, mval, off);
    mval *= (1.0f / 32.0f);
    const float f0 = o0 - mval * mean_shift[lane];
    float s = f0 * f0;
#pragma unroll
    for (int off = 16; off; off >>= 1) s += __shfl_xor_sync(full, s, off);
    const float sc0 = rsqrtf(s * (1.0f / 32.0f) + EPS_LN) * aw[lane];
    out[(size_t)warp * NODE_DIM + lane] = f0 * sc0 + ab[lane];

    float vx = 0.0f, vy = 0.0f, vz = 0.0f, msv = 0.0f;
    if (lane < 16) {
        vx = seg[32 + 3 * lane + 0] * inv + na[32 + 3 * lane + 0];
        vy = seg[32 + 3 * lane + 1] * inv + na[32 + 3 * lane + 1];
        vz = seg[32 + 3 * lane + 2] * inv + na[32 + 3 * lane + 2];
        msv = mean_shift[32 + lane];
    }
    float mx = vx, my = vy, mz = vz;
#pragma unroll
    for (int off = 16; off; off >>= 1) {
        mx += __shfl_xor_sync(full, mx, off);
        my += __shfl_xor_sync(full, my, off);
        mz += __shfl_xor_sync(full, mz, off);
    }
    mx *= (1.0f / 16.0f); my *= (1.0f / 16.0f); mz *= (1.0f / 16.0f);
    const float fx = vx - mx * msv;
    const float fy = vy - my * msv;
    const float fz = vz - mz * msv;
    float sq = (lane < 16) ? (fx * fx + fy * fy + fz * fz) : 0.0f;
#pragma unroll
    for (int off = 16; off; off >>= 1) sq += __shfl_xor_sync(full, sq, off);
    if (lane < 16) {
        const float sc1 = rsqrtf(sq * (1.0f / 48.0f) + EPS_LN) * aw[32 + lane];
        out[(size_t)warp * NODE_DIM + 32 + 3 * lane + 0] = fx * sc1;
        out[(size_t)warp * NODE_DIM + 32 + 3 * lane + 1] = fy * sc1;
        out[(size_t)warp * NODE_DIM + 32 + 3 * lane + 2] = fz * sc1;
    }
}

// ---------------- launch ----------------
extern "C" void kernel_launch(void* const* d_in, const int* in_sizes, int n_in,
                              void* d_out, int out_size) {
    const float* node_attr  = (const float*)d_in[0];
    const float* edge_attr  = (const float*)d_in[1];
    const float* edge_sh    = (const float*)d_in[2];
    const float* fc_w1      = (const float*)d_in[3];
    const float* fc_b1      = (const float*)d_in[4];
    const float* fc_w2      = (const float*)d_in[5];
    const float* fc_b2      = (const float*)d_in[6];
    const float* mean_shift = (const float*)d_in[7];
    const float* aw         = (const float*)d_in[8];
    const float* ab         = (const float*)d_in[9];
    const int*   edge_index = (const int*)d_in[10];
    float* out = (float*)d_out;

    cudaFuncSetAttribute(edge_kernel, cudaFuncAttributeMaxDynamicSharedMemorySize, (int)EDGE_SMEM);

    void* seg_ptr = nullptr;
    void* cnt_ptr = nullptr;
    cudaGetSymbolAddress(&seg_ptr, g_seg);
    cudaGetSymbolAddress(&cnt_ptr, g_cnt);
    cudaMemsetAsync(seg_ptr, 0, sizeof(float) * (size_t)N_NODES * NODE_DIM);
    cudaMemsetAsync(cnt_ptr, 0, sizeof(float) * N_NODES);

    prep_kernel<<<161, 256>>>(fc_w1, fc_w2);
    edge_kernel<<<NTILES, ETHREADS, EDGE_SMEM>>>(node_attr, edge_attr, edge_sh, fc_b1, fc_b2, edge_index);
    node_kernel<<<(N_NODES * 32 + 255) / 256, 256>>>(node_attr, mean_shift, aw, ab, out);
}